// round 10
// baseline (speedup 1.0000x reference)
#include <cuda_runtime.h>
#include <cuda_bf16.h>

// Shapes (fixed)
#define BB   8
#define NN   16384
#define SS   1024
#define TT   2
#define TPB  128
#define NPT  8

// Per-block result slots — every slot written on every call, no reset needed.
__device__ float  g_nsum[384];            // roles A,B: per-block n-side sums
__device__ float  g_pmin[16 * 24576];     // roles C,D: per-chunk partial mins
__device__ float  g_csum[128];            // role E: consistency block sums
__device__ double g_f1[48], g_f2[48];     // final1 partials (chamfer1/2 s-side)

__device__ __forceinline__ float block_reduce_sum(float v, float* sh) {
    #pragma unroll
    for (int o = 16; o > 0; o >>= 1) v += __shfl_down_sync(0xffffffffu, v, o);
    int lane = threadIdx.x & 31, w = threadIdx.x >> 5;
    if (lane == 0) sh[w] = v;
    __syncthreads();
    float r = 0.f;
    if (w == 0) {
        r = (lane < (int)(blockDim.x >> 5)) ? sh[lane] : 0.f;
        #pragma unroll
        for (int o = 16; o > 0; o >>= 1) r += __shfl_down_sync(0xffffffffu, r, o);
    }
    return r; // thread 0
}

// Fused kernel: 896 blocks x 128 threads. Every chamfer block: 1024x1024 pairs.
//  [0,128)   A: n-side chamfer1  (gt vs sp)          -> g_nsum[blk]
//  [128,384) B: n-side chamfer2  (tgt vs tsp)        -> g_nsum[blk]
//  [384,512) C: s-side chamfer1  partial mins        -> g_pmin[chunk][b*SS+s]
//  [512,768) D: s-side chamfer2  partial mins        -> g_pmin[chunk][8192+tb*SS+s]
//  [768,896) E: consistency MSE                      -> g_csum[blk-768]
__global__ void __launch_bounds__(TPB) k_fused(
        const float* __restrict__ gt, const float* __restrict__ sp,
        const float* __restrict__ tgt, const float* __restrict__ tsp,
        const float* __restrict__ tm) {
    __shared__ float4 ypts[1024];   // (-2x,-2y,-2z,|p|^2)
    __shared__ float red[32];
    int blk = blockIdx.x;
    int tid = threadIdx.x;

    if (blk >= 768) {
        // ---- consistency term ----
        int i = (blk - 768) * TPB + tid;      // 0..16383
        int t = i >> 13;
        int rem = i & 8191;
        const float* p = sp + 3 * rem;
        float a = p[0], b = p[1], c = p[2];
        const float* M = tm + 9 * t;
        float acc = 0.f;
        #pragma unroll
        for (int e = 0; e < 3; e++) {
            float v = fmaf(a, M[e], fmaf(b, M[3 + e], c * M[6 + e]));
            float diff = v - tsp[(size_t)i * 3 + e];
            acc = fmaf(diff, diff, acc);
        }
        float bsum = block_reduce_sum(acc, red);
        if (tid == 0) g_csum[blk - 768] = bsum;
        return;
    }

    const float* smem_src;   // 1024 pts -> smem tile
    const float* thr_src;    // 1024 pts -> registers (8 per thread)
    bool nside;
    int target;              // g_pmin row base for s-side

    if (blk < 128) {                       // A
        int b = blk >> 4, chunk = blk & 15;
        smem_src = sp + (size_t)b * SS * 3;
        thr_src  = gt + (size_t)b * NN * 3 + (size_t)chunk * 1024 * 3;
        nside = true; target = 0;
    } else if (blk < 384) {                // B
        int idx = blk - 128, tb = idx >> 4, chunk = idx & 15;
        smem_src = tsp + (size_t)tb * SS * 3;
        thr_src  = tgt + (size_t)tb * NN * 3 + (size_t)chunk * 1024 * 3;
        nside = true; target = 0;
    } else if (blk < 512) {                // C
        int idx = blk - 384, b = idx >> 4, chunk = idx & 15;
        smem_src = gt + (size_t)b * NN * 3 + (size_t)chunk * 1024 * 3;
        thr_src  = sp + (size_t)b * SS * 3;
        nside = false; target = chunk * 24576 + b * SS;
    } else {                               // D
        int idx = blk - 512, tb = idx >> 4, chunk = idx & 15;
        smem_src = tgt + (size_t)tb * NN * 3 + (size_t)chunk * 1024 * 3;
        thr_src  = tsp + (size_t)tb * SS * 3;
        nside = false; target = chunk * 24576 + 8192 + tb * SS;
    }

    // Shared tile: (-2x, -2y, -2z, x^2+y^2+z^2)
    for (int i = tid; i < 1024; i += TPB) {
        const float* p = smem_src + 3 * i;
        float a = p[0], b = p[1], c = p[2];
        float sqv = fmaf(a, a, fmaf(b, b, c * c));
        ypts[i] = make_float4(-2.f * a, -2.f * b, -2.f * c, sqv);
    }
    __syncthreads();

    // 8 thread-private points
    float x0[NPT], x1[NPT], x2[NPT], sqx[NPT], mn[NPT];
    #pragma unroll
    for (int k = 0; k < NPT; k++) {
        const float* p = thr_src + 3 * (tid + k * TPB);
        x0[k] = p[0]; x1[k] = p[1]; x2[k] = p[2];
        sqx[k] = fmaf(x0[k], x0[k], fmaf(x1[k], x1[k], x2[k] * x2[k]));
        mn[k] = 3.4e38f;
    }

    // Core loop: per s = 1 LDS.128 + 24 FFMA + 8 FMNMX for 8 pairs
    #pragma unroll 2
    for (int s = 0; s < 1024; s++) {
        float4 y = ypts[s];
        #pragma unroll
        for (int k = 0; k < NPT; k++) {
            float v = fmaf(y.x, x0[k], y.w);
            v = fmaf(y.y, x1[k], v);
            v = fmaf(y.z, x2[k], v);
            mn[k] = fminf(mn[k], v);
        }
    }

    if (nside) {
        float s8 = 0.f;
        #pragma unroll
        for (int k = 0; k < NPT; k++) s8 += mn[k] + sqx[k];
        float bs = block_reduce_sum(s8, red);
        if (tid == 0) g_nsum[blk] = bs;
    } else {
        #pragma unroll
        for (int k = 0; k < NPT; k++)
            g_pmin[target + tid + k * TPB] = mn[k] + sqx[k];
    }
}

// Stage 1: min over 16 chunks per (b,s) row, partial sums per block.
// 48 blocks x 256 threads; block handles 512 rows (either all chamfer1 or all chamfer2).
__global__ void k_final1() {
    __shared__ float red[32];
    int row0 = blockIdx.x * 512;
    float s = 0.f;
    for (int r = row0 + threadIdx.x; r < row0 + 512; r += 256) {
        float m = g_pmin[r];
        #pragma unroll
        for (int c = 1; c < 16; c++) m = fminf(m, g_pmin[c * 24576 + r]);
        s += m;
    }
    float bs = block_reduce_sum(s, red);
    if (threadIdx.x == 0) {
        if (blockIdx.x < 16) { g_f1[blockIdx.x] = (double)bs; g_f2[blockIdx.x] = 0.0; }
        else                 { g_f1[blockIdx.x] = 0.0;        g_f2[blockIdx.x] = (double)bs; }
    }
}

// Stage 2: combine everything.
__global__ void k_final2(float* __restrict__ out) {
    __shared__ double sh[32 * 5];
    double v1 = 0, v2 = 0, n1 = 0, n2 = 0, cs = 0;
    int t = threadIdx.x;             // 512 threads
    if (t < 48) { v1 = g_f1[t]; v2 = g_f2[t]; }
    if (t < 128) n1 = (double)g_nsum[t];
    if (t < 256) n2 = (double)g_nsum[128 + t] + ((t < 128) ? (double)g_nsum[256 + t] : 0.0);
    if (t < 128) cs = (double)g_csum[t];
    #pragma unroll
    for (int o = 16; o > 0; o >>= 1) {
        v1 += __shfl_down_sync(0xffffffffu, v1, o);
        v2 += __shfl_down_sync(0xffffffffu, v2, o);
        n1 += __shfl_down_sync(0xffffffffu, n1, o);
        n2 += __shfl_down_sync(0xffffffffu, n2, o);
        cs += __shfl_down_sync(0xffffffffu, cs, o);
    }
    int lane = t & 31, w = t >> 5;   // 16 warps
    if (lane == 0) {
        sh[w] = v1; sh[32 + w] = v2; sh[64 + w] = n1; sh[96 + w] = n2; sh[128 + w] = cs;
    }
    __syncthreads();
    if (t == 0) {
        double V1 = 0, V2 = 0, N1 = 0, N2 = 0, CS = 0;
        for (int j = 0; j < 16; j++) {
            V1 += sh[j]; V2 += sh[32 + j]; N1 += sh[64 + j]; N2 += sh[96 + j]; CS += sh[128 + j];
        }
        double mean_s1 = V1 / (double)(BB * SS);
        double mean_n1 = N1 / (double)(BB * NN);
        double c1 = 0.5 * (mean_s1 + mean_n1);
        double mean_s2 = V2 / (double)(TT * BB * SS);
        double mean_n2 = N2 / (double)(TT * BB * NN);
        double c2 = 0.5 * (mean_s2 + mean_n2);
        double cd = (c1 + c2) / (double)(TT + 1);
        double mse = CS / (double)(TT * BB * SS * 3) * 1000.0;
        out[0] = (float)(cd + mse);
    }
}

extern "C" void kernel_launch(void* const* d_in, const int* in_sizes, int n_in,
                              void* d_out, int out_size) {
    const float* gt  = (const float*)d_in[0];  // [B,N,3]
    const float* sp  = (const float*)d_in[1];  // [B,S,3]
    const float* tgt = (const float*)d_in[2];  // [T,B,N,3]
    const float* tsp = (const float*)d_in[3];  // [T,B,S,3]
    const float* tm  = (const float*)d_in[4];  // [T,3,3]
    float* out = (float*)d_out;

    k_fused<<<896, TPB>>>(gt, sp, tgt, tsp, tm);
    k_final1<<<48, 256>>>();
    k_final2<<<1, 512>>>(out);
}

// round 13
// speedup vs baseline: 1.1901x; 1.1901x over previous
#include <cuda_runtime.h>
#include <cuda_bf16.h>

// Shapes (fixed)
#define BB   8
#define NN   16384
#define SS   1024
#define TT   2
#define TPB  128
#define NPT  8
#define YT   512          // Y tile (smem) size

// Partial-min scratch (written fully every call; no reset needed)
//  P1N: [2][131072]  chamfer1 n-side   off 0
//  P2N: [2][262144]  chamfer2 n-side   off 262144
//  P1S: [32][8192]   chamfer1 s-side   off 786432
//  P2S: [32][16384]  chamfer2 s-side   off 1048576
#define P1N_OFF 0
#define P2N_OFF 262144
#define P1S_OFF 786432
#define P2S_OFF 1048576
__device__ float  g_pmin[1572864];      // 6 MB
__device__ float  g_csum[128];          // consistency block sums
__device__ double g_red[128];           // weighted partials from k_red

__device__ __forceinline__ float block_reduce_sum(float v, float* sh) {
    #pragma unroll
    for (int o = 16; o > 0; o >>= 1) v += __shfl_down_sync(0xffffffffu, v, o);
    int lane = threadIdx.x & 31, w = threadIdx.x >> 5;
    if (lane == 0) sh[w] = v;
    __syncthreads();
    float r = 0.f;
    if (w == 0) {
        r = (lane < (int)(blockDim.x >> 5)) ? sh[lane] : 0.f;
        #pragma unroll
        for (int o = 16; o > 0; o >>= 1) r += __shfl_down_sync(0xffffffffu, r, o);
    }
    return r; // thread 0
}

// 1664 blocks x 128 threads. Chamfer tiles are uniform: 1024 X pts (8/thread)
// vs 512 Y pts (smem); every chamfer block writes 1024 partial mins.
//  [0,256)     A: c1 n-side  (X=gt chunk,  Y=sp half)   -> P1N
//  [256,768)   B: c2 n-side  (X=tgt chunk, Y=tsp half)  -> P2N
//  [768,1024)  C: c1 s-side  (X=sp,        Y=gt 512)    -> P1S
//  [1024,1536) D: c2 s-side  (X=tsp,       Y=tgt 512)   -> P2S
//  [1536,1664) E: consistency                            -> g_csum
__global__ void __launch_bounds__(TPB) k_fused(
        const float* __restrict__ gt, const float* __restrict__ sp,
        const float* __restrict__ tgt, const float* __restrict__ tsp,
        const float* __restrict__ tm) {
    __shared__ float4 ypts[YT];     // (-2x,-2y,-2z,|p|^2)
    __shared__ float red[32];
    int blk = blockIdx.x;
    int tid = threadIdx.x;

    if (blk >= 1536) {
        // ---- consistency term ----
        int i = (blk - 1536) * TPB + tid;     // 0..16383
        int t = i >> 13;
        int rem = i & 8191;
        const float* p = sp + 3 * rem;
        float a = p[0], b = p[1], c = p[2];
        const float* M = tm + 9 * t;
        float acc = 0.f;
        #pragma unroll
        for (int e = 0; e < 3; e++) {
            float v = fmaf(a, M[e], fmaf(b, M[3 + e], c * M[6 + e]));
            float diff = v - tsp[(size_t)i * 3 + e];
            acc = fmaf(diff, diff, acc);
        }
        float bsum = block_reduce_sum(acc, red);
        if (tid == 0) g_csum[blk - 1536] = bsum;
        return;
    }

    const float* ysrc;   // 512 pts -> smem
    const float* xsrc;   // 1024 pts -> regs (8/thread)
    float* outp;         // 1024 partial mins

    if (blk < 256) {                       // A
        int b = blk >> 5, xc = (blk >> 1) & 15, yh = blk & 1;
        xsrc = gt + ((size_t)b * NN + (size_t)xc * 1024) * 3;
        ysrc = sp + ((size_t)b * SS + (size_t)yh * YT) * 3;
        outp = g_pmin + P1N_OFF + yh * 131072 + b * NN + xc * 1024;
    } else if (blk < 768) {                // B
        int idx = blk - 256;
        int tb = idx >> 5, xc = (idx >> 1) & 15, yh = idx & 1;
        xsrc = tgt + ((size_t)tb * NN + (size_t)xc * 1024) * 3;
        ysrc = tsp + ((size_t)tb * SS + (size_t)yh * YT) * 3;
        outp = g_pmin + P2N_OFF + yh * 262144 + tb * NN + xc * 1024;
    } else if (blk < 1024) {               // C
        int idx = blk - 768;
        int b = idx >> 5, yc = idx & 31;
        xsrc = sp + (size_t)b * SS * 3;
        ysrc = gt + ((size_t)b * NN + (size_t)yc * YT) * 3;
        outp = g_pmin + P1S_OFF + yc * 8192 + b * SS;
    } else {                               // D
        int idx = blk - 1024;
        int tb = idx >> 5, yc = idx & 31;
        xsrc = tsp + (size_t)tb * SS * 3;
        ysrc = tgt + ((size_t)tb * NN + (size_t)yc * YT) * 3;
        outp = g_pmin + P2S_OFF + yc * 16384 + tb * SS;
    }

    // Shared tile: (-2x, -2y, -2z, |p|^2)
    for (int i = tid; i < YT; i += TPB) {
        const float* p = ysrc + 3 * i;
        float a = p[0], b = p[1], c = p[2];
        float sqv = fmaf(a, a, fmaf(b, b, c * c));
        ypts[i] = make_float4(-2.f * a, -2.f * b, -2.f * c, sqv);
    }
    __syncthreads();

    // 8 thread-private X points (|x|^2 recomputed after the loop — not live state)
    float x0[NPT], x1[NPT], x2[NPT], mn[NPT];
    #pragma unroll
    for (int k = 0; k < NPT; k++) {
        const float* p = xsrc + 3 * (tid + k * TPB);
        x0[k] = p[0]; x1[k] = p[1]; x2[k] = p[2];
        mn[k] = 3.4e38f;
    }

    // Core loop: per s = 1 broadcast LDS.128 + 24 FFMA + 8 FMNMX for 8 pairs
    #pragma unroll 8
    for (int s = 0; s < YT; s++) {
        float4 y = ypts[s];
        #pragma unroll
        for (int k = 0; k < NPT; k++) {
            float v = fmaf(y.x, x0[k], y.w);
            v = fmaf(y.y, x1[k], v);
            v = fmaf(y.z, x2[k], v);
            mn[k] = fminf(mn[k], v);
        }
    }

    #pragma unroll
    for (int k = 0; k < NPT; k++) {
        float sq = fmaf(x0[k], x0[k], fmaf(x1[k], x1[k], x2[k] * x2[k]));
        outp[tid + k * TPB] = mn[k] + sq;
    }
}

// Weighted reduction of all partial-min arrays + consistency into 128 doubles.
// cd = [ (S1s/8192 + S1n/131072)/2 + (S2s/16384 + S2n/262144)/2 ] / 3
// mse = CS/49152 * 1000
#define W1N (1.0 / (131072.0 * 6.0))
#define W1S (1.0 / (8192.0   * 6.0))
#define W2N (1.0 / (262144.0 * 6.0))
#define W2S (1.0 / (16384.0  * 6.0))
#define WC  (1000.0 / 49152.0)

__global__ void k_red() {
    __shared__ double sh[8];
    int bid = blockIdx.x, tid = threadIdx.x;     // 128 blocks x 256 threads
    double acc = 0.0;

    // c1 n-side: 1024 entries per block, min over 2 halves
    {
        int base = bid * 1024;
        for (int j = tid; j < 1024; j += 256) {
            int i = base + j;
            acc += W1N * (double)fminf(g_pmin[P1N_OFF + i], g_pmin[P1N_OFF + 131072 + i]);
        }
    }
    // c2 n-side: 2048 entries per block
    {
        int base = bid * 2048;
        for (int j = tid; j < 2048; j += 256) {
            int i = base + j;
            acc += W2N * (double)fminf(g_pmin[P2N_OFF + i], g_pmin[P2N_OFF + 262144 + i]);
        }
    }
    // c1 s-side: 64 rows per block, min over 32 chunks
    if (tid < 64) {
        int r = bid * 64 + tid;
        float m = g_pmin[P1S_OFF + r];
        #pragma unroll
        for (int c = 1; c < 32; c++) m = fminf(m, g_pmin[P1S_OFF + c * 8192 + r]);
        acc += W1S * (double)m;
    }
    // c2 s-side: 128 rows per block, min over 32 chunks
    if (tid < 128) {
        int r = bid * 128 + tid;
        float m = g_pmin[P2S_OFF + r];
        #pragma unroll
        for (int c = 1; c < 32; c++) m = fminf(m, g_pmin[P2S_OFF + c * 16384 + r]);
        acc += W2S * (double)m;
    }

    #pragma unroll
    for (int o = 16; o > 0; o >>= 1) acc += __shfl_down_sync(0xffffffffu, acc, o);
    int lane = tid & 31, w = tid >> 5;
    if (lane == 0) sh[w] = acc;
    __syncthreads();
    if (tid == 0) {
        double t = WC * (double)g_csum[bid];
        for (int j = 0; j < 8; j++) t += sh[j];
        g_red[bid] = t;
    }
}

__global__ void k_final(float* __restrict__ out) {
    __shared__ double sh[4];
    double v = g_red[threadIdx.x];               // 128 threads
    #pragma unroll
    for (int o = 16; o > 0; o >>= 1) v += __shfl_down_sync(0xffffffffu, v, o);
    int lane = threadIdx.x & 31, w = threadIdx.x >> 5;
    if (lane == 0) sh[w] = v;
    __syncthreads();
    if (threadIdx.x == 0)
        out[0] = (float)(sh[0] + sh[1] + sh[2] + sh[3]);
}

extern "C" void kernel_launch(void* const* d_in, const int* in_sizes, int n_in,
                              void* d_out, int out_size) {
    const float* gt  = (const float*)d_in[0];  // [B,N,3]
    const float* sp  = (const float*)d_in[1];  // [B,S,3]
    const float* tgt = (const float*)d_in[2];  // [T,B,N,3]
    const float* tsp = (const float*)d_in[3];  // [T,B,S,3]
    const float* tm  = (const float*)d_in[4];  // [T,3,3]
    float* out = (float*)d_out;

    k_fused<<<1664, TPB>>>(gt, sp, tgt, tsp, tm);
    k_red<<<128, 256>>>();
    k_final<<<1, 128>>>(out);
}